// round 13
// baseline (speedup 1.0000x reference)
#include <cuda_runtime.h>
#include <cuda_bf16.h>
#include <math.h>

// ============================================================================
// Hyperbolic linear layer via mma.sync (HMMA bf16, fp32 acc), sm_103-safe PTX.
//   v   = xscale(row) * (x @ W^T) + b ;  out = proj(exp_map_zero(v))
// Split-bf16 3-term GEMM: x@W^T ~= xh@Wh^T + xh@Wl^T + xl@Wh^T  (err ~2^-17)
// R5: converted-A double-buffered; conversion interleaved INTO the MMA loop
//     (LDG regs -> cvt -> STS in the MMA shadow). One sync per chunk.
// ============================================================================

#define NT 512

// SMEM layout (bytes)
#define A_ST 18432               // 128 rows * 144B per stage
#define B_ST 36864               // 256 rows * 144B per stage
#define AHI  0                   // 2 stages
#define ALO  36864               // 2 stages
#define BHI  73728               // 2 stages
#define BLO  147456              // 2 stages
#define CTRL 221184
#define SMEM_BYTES (CTRL + 4096)

// W split into bf16 hi/lo, [n][k] row-major.
__device__ __align__(16) unsigned short g_Whi[65536];
__device__ __align__(16) unsigned short g_Wlo[65536];

__global__ void prep_W_kernel(const float* __restrict__ W)
{
    int n = blockIdx.x, k = threadIdx.x;
    float w = W[n * 256 + k];
    __nv_bfloat16 hi = __float2bfloat16(w);
    float hif = __bfloat162float(hi);
    __nv_bfloat16 lo = __float2bfloat16(w - hif);
    g_Whi[n * 256 + k] = __bfloat16_as_ushort(hi);
    g_Wlo[n * 256 + k] = __bfloat16_as_ushort(lo);
}

// ---------------------------------------------------------------------------
__device__ __forceinline__ unsigned smem_u32(const void* p) {
    unsigned a;
    asm("{ .reg .u64 t; cvta.to.shared.u64 t, %1; cvt.u32.u64 %0, t; }"
        : "=r"(a) : "l"(p));
    return a;
}
__device__ __forceinline__ void cpasync16(unsigned dst, const void* src) {
    asm volatile("cp.async.cg.shared.global [%0], [%1], 16;"
                 :: "r"(dst), "l"(src));
}
#define CP_COMMIT() asm volatile("cp.async.commit_group;")
#define CP_WAIT0()  asm volatile("cp.async.wait_group 0;")

#define LDSM4(r, addr) \
    asm volatile("ldmatrix.sync.aligned.m8n8.x4.shared.b16 {%0,%1,%2,%3}, [%4];" \
        : "=r"((r)[0]), "=r"((r)[1]), "=r"((r)[2]), "=r"((r)[3]) : "r"(addr))

#define MMA(d, a, b0, b1) \
    asm volatile("mma.sync.aligned.m16n8k16.row.col.f32.bf16.bf16.f32 " \
        "{%0,%1,%2,%3}, {%4,%5,%6,%7}, {%8,%9}, {%0,%1,%2,%3};" \
        : "+f"((d)[0]), "+f"((d)[1]), "+f"((d)[2]), "+f"((d)[3]) \
        : "r"((a)[0]), "r"((a)[1]), "r"((a)[2]), "r"((a)[3]), "r"(b0), "r"(b1))

__device__ __forceinline__ unsigned pack_bf16x2(float lo, float hi) {
    unsigned r;
    asm("cvt.rn.bf16x2.f32 %0, %1, %2;" : "=r"(r) : "f"(hi), "f"(lo));
    return r;
}

// cp.async B chunk c into stage s (hi + lo).
__device__ __forceinline__ void issueB(unsigned smb, int tid, int c, int s)
{
    #pragma unroll
    for (int i = 0; i < 4; i++) {
        int p = tid + i * NT;          // 0..2047
        int n = p >> 3, seg = p & 7;
        unsigned dst = smb + n * 144 + seg * 16 + s * B_ST;
        cpasync16(dst + BHI, (const char*)g_Whi + n * 512 + c * 128 + seg * 16);
        cpasync16(dst + BLO, (const char*)g_Wlo + n * 512 + c * 128 + seg * 16);
    }
}

// Convert 16 fp32 (4x float4, this thread's slice of a K-chunk) into bf16
// hi/lo stage s. thread: row r = tid>>2, seg = tid&3. STS conflict-free.
__device__ __forceinline__ void convertRegs(char* sm, int tid, int s,
                                            const float4* v4, float& ssx)
{
    const int r = tid >> 2, seg = tid & 3;
    char* dH = sm + AHI + s * A_ST + r * 144 + seg * 32;
    char* dL = sm + ALO + s * A_ST + r * 144 + seg * 32;
    unsigned uh[8], ul[8];
    #pragma unroll
    for (int i = 0; i < 4; i++) {
        float4 v = v4[i];
        ssx = fmaf(v.x, v.x, fmaf(v.y, v.y, fmaf(v.z, v.z, fmaf(v.w, v.w, ssx))));
        unsigned h0 = pack_bf16x2(v.x, v.y);
        unsigned h1 = pack_bf16x2(v.z, v.w);
        float hx = __uint_as_float(h0 << 16);
        float hy = __uint_as_float(h0 & 0xFFFF0000u);
        float hz = __uint_as_float(h1 << 16);
        float hw = __uint_as_float(h1 & 0xFFFF0000u);
        uh[2 * i]     = h0;
        uh[2 * i + 1] = h1;
        ul[2 * i]     = pack_bf16x2(v.x - hx, v.y - hy);
        ul[2 * i + 1] = pack_bf16x2(v.z - hz, v.w - hw);
    }
    ((uint4*)dH)[0] = make_uint4(uh[0], uh[1], uh[2], uh[3]);
    ((uint4*)dH)[1] = make_uint4(uh[4], uh[5], uh[6], uh[7]);
    ((uint4*)dL)[0] = make_uint4(ul[0], ul[1], ul[2], ul[3]);
    ((uint4*)dL)[1] = make_uint4(ul[4], ul[5], ul[6], ul[7]);
}

__global__ __launch_bounds__(NT, 1)
void hyper_hmma_kernel(const float* __restrict__ x,
                       const float* __restrict__ bias,
                       float* __restrict__ out)
{
    extern __shared__ char sm[];
    const unsigned smb = smem_u32(sm);
    const int tid  = threadIdx.x;
    const int lane = tid & 31;
    const int wid  = tid >> 5;
    const int wm   = wid & 3;          // m group (32 rows)
    const int wn   = wid >> 2;         // n group (64 cols)
    const long row0 = (long)blockIdx.x * 128;

    float* b_s      = (float*)(sm + CTRL);          // 256 f
    float* xscale_s = (float*)(sm + CTRL + 1024);   // 128 f
    float* part_s   = (float*)(sm + CTRL + 1536);   // 512 f
    float* factor_s = (float*)(sm + CTRL + 3584);   // 128 f

    if (tid < 256) b_s[tid] = bias[tid];

    const unsigned aHiB = smb + AHI + (wm * 32 + (lane & 15)) * 144 + (lane >> 4) * 16;
    const unsigned aLoB = aHiB + (ALO - AHI);
    const unsigned bHiB = smb + BHI + (wn * 64 + (lane & 15)) * 144 + (lane >> 4) * 16;
    const unsigned bLoB = bHiB + (BLO - BHI);

    // A load geometry for this thread (row r, 16-float segment seg)
    const int ar = tid >> 2, aseg = tid & 3;
    const float* aptr = x + (row0 + ar) * 256 + aseg * 16;

    float acc[16][4];
    #pragma unroll
    for (int i = 0; i < 16; i++)
        #pragma unroll
        for (int j = 0; j < 4; j++) acc[i][j] = 0.f;

    float ssx = 0.f;

    // prologue: B0 in flight; convert A chunk0 from LDG regs into stage 0.
    issueB(smb, tid, 0, 0);
    CP_COMMIT();
    {
        float4 a0[4];
        #pragma unroll
        for (int i = 0; i < 4; i++) a0[i] = *(const float4*)(aptr + i * 4);
        convertRegs(sm, tid, 0, a0, ssx);
    }

    // ------------------------- mainloop: 4 K-chunks -------------------------
    #pragma unroll 1
    for (int c = 0; c < 4; c++) {
        const int s = c & 1;
        CP_WAIT0();                   // B(c) landed
        __syncthreads();              // B(c) + convA(c) visible to all

        float4 anx[4];
        if (c < 3) {
            issueB(smb, tid, c + 1, s ^ 1);
            CP_COMMIT();
            const float* ap = aptr + (c + 1) * 64;
            #pragma unroll
            for (int i = 0; i < 4; i++) anx[i] = *(const float4*)(ap + i * 4);
        }

        const unsigned aH = aHiB + s * A_ST;
        const unsigned aL = aLoB + s * A_ST;
        const unsigned bH = bHiB + s * B_ST;
        const unsigned bL = bLoB + s * B_ST;
        #pragma unroll
        for (int k16 = 0; k16 < 4; k16++) {
            unsigned ah[2][4], al[2][4];
            #pragma unroll
            for (int mi = 0; mi < 2; mi++) {
                LDSM4(ah[mi], aH + mi * 2304 + k16 * 32);
                LDSM4(al[mi], aL + mi * 2304 + k16 * 32);
            }
            #pragma unroll
            for (int nn = 0; nn < 4; nn++) {
                unsigned bh[4], bl[4];
                LDSM4(bh, bH + nn * 2304 + k16 * 32);
                LDSM4(bl, bL + nn * 2304 + k16 * 32);
                #pragma unroll
                for (int mi = 0; mi < 2; mi++) {
                    #pragma unroll
                    for (int hn = 0; hn < 2; hn++) {
                        float* d = acc[mi * 8 + nn * 2 + hn];
                        MMA(d, ah[mi], bh[hn], bh[hn + 2]);
                        MMA(d, ah[mi], bl[hn], bl[hn + 2]);
                        MMA(d, al[mi], bh[hn], bh[hn + 2]);
                    }
                }
            }
            // mid-loop: convert next-chunk A regs into the other stage
            if (k16 == 1 && c < 3)
                convertRegs(sm, tid, s ^ 1, anx, ssx);
        }
    }

    // log-map scale per row (4 lanes share row ar)
    {
        float t = ssx;
        t += __shfl_xor_sync(0xffffffffu, t, 1);
        t += __shfl_xor_sync(0xffffffffu, t, 2);
        if ((tid & 3) == 0) {
            float xn = fmaxf(sqrtf(t), 1e-6f);
            float sc = fminf(0.1f * xn, 1.0f - 1e-6f);
            xscale_s[ar] = atanhf(sc) / (0.1f * xn);
        }
    }
    __syncthreads();

    // ------------------------- epilogue -------------------------
    const int rsub = lane >> 2;
    float xs[2][2];
    #pragma unroll
    for (int mi = 0; mi < 2; mi++)
        #pragma unroll
        for (int h = 0; h < 2; h++)
            xs[mi][h] = xscale_s[wm * 32 + mi * 16 + h * 8 + rsub];

    float2 bb[8];
    #pragma unroll
    for (int ni = 0; ni < 8; ni++) {
        int col = wn * 64 + ni * 8 + (lane & 3) * 2;
        bb[ni] = make_float2(b_s[col], b_s[col + 1]);
    }

    float ss[2][2] = {{0.f, 0.f}, {0.f, 0.f}};
    #pragma unroll
    for (int mi = 0; mi < 2; mi++) {
        #pragma unroll
        for (int ni = 0; ni < 8; ni++) {
            float* d = acc[mi * 8 + ni];
            float v0 = fmaf(d[0], xs[mi][0], bb[ni].x);
            float v1 = fmaf(d[1], xs[mi][0], bb[ni].y);
            float v2 = fmaf(d[2], xs[mi][1], bb[ni].x);
            float v3 = fmaf(d[3], xs[mi][1], bb[ni].y);
            d[0] = v0; d[1] = v1; d[2] = v2; d[3] = v3;
            ss[mi][0] = fmaf(v0, v0, fmaf(v1, v1, ss[mi][0]));
            ss[mi][1] = fmaf(v2, v2, fmaf(v3, v3, ss[mi][1]));
        }
    }
    #pragma unroll
    for (int mi = 0; mi < 2; mi++)
        #pragma unroll
        for (int h = 0; h < 2; h++) {
            float t = ss[mi][h];
            t += __shfl_xor_sync(0xffffffffu, t, 1);
            t += __shfl_xor_sync(0xffffffffu, t, 2);
            if ((lane & 3) == 0)
                part_s[wn * 128 + wm * 32 + mi * 16 + h * 8 + rsub] = t;
        }
    __syncthreads();
    if (tid < 128) {
        float tot = part_s[tid] + part_s[128 + tid] + part_s[256 + tid] + part_s[384 + tid];
        float vn = fmaxf(sqrtf(tot), 1e-6f);
        float g  = tanhf(0.1f * vn) / (0.1f * vn);
        float rn = fmaxf(g * vn, 1e-6f);
        float cl = fminf(rn, 10.0f - 2e-6f);
        factor_s[tid] = g * (cl / rn);
    }
    __syncthreads();

    #pragma unroll
    for (int mi = 0; mi < 2; mi++) {
        #pragma unroll
        for (int h = 0; h < 2; h++) {
            const int row = wm * 32 + mi * 16 + h * 8 + rsub;
            const float f = factor_s[row];
            float* orow = out + (row0 + row) * 256;
            #pragma unroll
            for (int ni = 0; ni < 8; ni++) {
                float* d = acc[mi * 8 + ni];
                int col = wn * 64 + ni * 8 + (lane & 3) * 2;
                float2 o;
                o.x = d[h * 2]     * f;
                o.y = d[h * 2 + 1] * f;
                *(float2*)(orow + col) = o;
            }
        }
    }
}

extern "C" void kernel_launch(void* const* d_in, const int* in_sizes, int n_in,
                              void* d_out, int out_size)
{
    const float* x = (const float*)d_in[0];
    const float* W = (const float*)d_in[1];
    const float* b = (const float*)d_in[2];
    float* out = (float*)d_out;

    prep_W_kernel<<<256, 256>>>(W);

    cudaFuncSetAttribute(hyper_hmma_kernel,
                         cudaFuncAttributeMaxDynamicSharedMemorySize, SMEM_BYTES);
    const int nrows = in_sizes[0] / 256;
    hyper_hmma_kernel<<<nrows / 128, NT, SMEM_BYTES>>>(x, b, out);
}

// round 14
// speedup vs baseline: 1.0037x; 1.0037x over previous
#include <cuda_runtime.h>
#include <cuda_bf16.h>
#include <math.h>

// ============================================================================
// Hyperbolic linear layer via mma.sync (HMMA bf16, fp32 acc), sm_103-safe PTX.
//   v   = xscale(row) * (x @ W^T) + b ;  out = proj(exp_map_zero(v))
// Split-bf16 3-term GEMM: x@W^T ~= xh@Wh^T + xh@Wl^T + xl@Wh^T  (err ~2^-17)
// R5: converted-A double-buffered; conversion interleaved INTO the MMA loop
//     (LDG regs -> cvt -> STS in the MMA shadow). One sync per chunk.
// ============================================================================

#define NT 512

// SMEM layout (bytes)
#define A_ST 18432               // 128 rows * 144B per stage
#define B_ST 36864               // 256 rows * 144B per stage
#define AHI  0                   // 2 stages
#define ALO  36864               // 2 stages
#define BHI  73728               // 2 stages
#define BLO  147456              // 2 stages
#define CTRL 221184
#define SMEM_BYTES (CTRL + 4096)

// W split into bf16 hi/lo, [n][k] row-major.
__device__ __align__(16) unsigned short g_Whi[65536];
__device__ __align__(16) unsigned short g_Wlo[65536];

__global__ void prep_W_kernel(const float* __restrict__ W)
{
    int n = blockIdx.x, k = threadIdx.x;
    float w = W[n * 256 + k];
    __nv_bfloat16 hi = __float2bfloat16(w);
    float hif = __bfloat162float(hi);
    __nv_bfloat16 lo = __float2bfloat16(w - hif);
    g_Whi[n * 256 + k] = __bfloat16_as_ushort(hi);
    g_Wlo[n * 256 + k] = __bfloat16_as_ushort(lo);
}

// ---------------------------------------------------------------------------
__device__ __forceinline__ unsigned smem_u32(const void* p) {
    unsigned a;
    asm("{ .reg .u64 t; cvta.to.shared.u64 t, %1; cvt.u32.u64 %0, t; }"
        : "=r"(a) : "l"(p));
    return a;
}
__device__ __forceinline__ void cpasync16(unsigned dst, const void* src) {
    asm volatile("cp.async.cg.shared.global [%0], [%1], 16;"
                 :: "r"(dst), "l"(src));
}
#define CP_COMMIT() asm volatile("cp.async.commit_group;")
#define CP_WAIT0()  asm volatile("cp.async.wait_group 0;")

#define LDSM4(r, addr) \
    asm volatile("ldmatrix.sync.aligned.m8n8.x4.shared.b16 {%0,%1,%2,%3}, [%4];" \
        : "=r"((r)[0]), "=r"((r)[1]), "=r"((r)[2]), "=r"((r)[3]) : "r"(addr))

#define MMA(d, a, b0, b1) \
    asm volatile("mma.sync.aligned.m16n8k16.row.col.f32.bf16.bf16.f32 " \
        "{%0,%1,%2,%3}, {%4,%5,%6,%7}, {%8,%9}, {%0,%1,%2,%3};" \
        : "+f"((d)[0]), "+f"((d)[1]), "+f"((d)[2]), "+f"((d)[3]) \
        : "r"((a)[0]), "r"((a)[1]), "r"((a)[2]), "r"((a)[3]), "r"(b0), "r"(b1))

__device__ __forceinline__ unsigned pack_bf16x2(float lo, float hi) {
    unsigned r;
    asm("cvt.rn.bf16x2.f32 %0, %1, %2;" : "=r"(r) : "f"(hi), "f"(lo));
    return r;
}

// cp.async B chunk c into stage s (hi + lo).
__device__ __forceinline__ void issueB(unsigned smb, int tid, int c, int s)
{
    #pragma unroll
    for (int i = 0; i < 4; i++) {
        int p = tid + i * NT;          // 0..2047
        int n = p >> 3, seg = p & 7;
        unsigned dst = smb + n * 144 + seg * 16 + s * B_ST;
        cpasync16(dst + BHI, (const char*)g_Whi + n * 512 + c * 128 + seg * 16);
        cpasync16(dst + BLO, (const char*)g_Wlo + n * 512 + c * 128 + seg * 16);
    }
}

// Convert 16 fp32 (4x float4, this thread's slice of a K-chunk) into bf16
// hi/lo stage s. thread: row r = tid>>2, seg = tid&3. STS conflict-free.
__device__ __forceinline__ void convertRegs(char* sm, int tid, int s,
                                            const float4* v4, float& ssx)
{
    const int r = tid >> 2, seg = tid & 3;
    char* dH = sm + AHI + s * A_ST + r * 144 + seg * 32;
    char* dL = sm + ALO + s * A_ST + r * 144 + seg * 32;
    unsigned uh[8], ul[8];
    #pragma unroll
    for (int i = 0; i < 4; i++) {
        float4 v = v4[i];
        ssx = fmaf(v.x, v.x, fmaf(v.y, v.y, fmaf(v.z, v.z, fmaf(v.w, v.w, ssx))));
        unsigned h0 = pack_bf16x2(v.x, v.y);
        unsigned h1 = pack_bf16x2(v.z, v.w);
        float hx = __uint_as_float(h0 << 16);
        float hy = __uint_as_float(h0 & 0xFFFF0000u);
        float hz = __uint_as_float(h1 << 16);
        float hw = __uint_as_float(h1 & 0xFFFF0000u);
        uh[2 * i]     = h0;
        uh[2 * i + 1] = h1;
        ul[2 * i]     = pack_bf16x2(v.x - hx, v.y - hy);
        ul[2 * i + 1] = pack_bf16x2(v.z - hz, v.w - hw);
    }
    ((uint4*)dH)[0] = make_uint4(uh[0], uh[1], uh[2], uh[3]);
    ((uint4*)dH)[1] = make_uint4(uh[4], uh[5], uh[6], uh[7]);
    ((uint4*)dL)[0] = make_uint4(ul[0], ul[1], ul[2], ul[3]);
    ((uint4*)dL)[1] = make_uint4(ul[4], ul[5], ul[6], ul[7]);
}

__global__ __launch_bounds__(NT, 1)
void hyper_hmma_kernel(const float* __restrict__ x,
                       const float* __restrict__ bias,
                       float* __restrict__ out)
{
    extern __shared__ char sm[];
    const unsigned smb = smem_u32(sm);
    const int tid  = threadIdx.x;
    const int lane = tid & 31;
    const int wid  = tid >> 5;
    const int wm   = wid & 3;          // m group (32 rows)
    const int wn   = wid >> 2;         // n group (64 cols)
    const long row0 = (long)blockIdx.x * 128;

    float* b_s      = (float*)(sm + CTRL);          // 256 f
    float* xscale_s = (float*)(sm + CTRL + 1024);   // 128 f
    float* part_s   = (float*)(sm + CTRL + 1536);   // 512 f
    float* factor_s = (float*)(sm + CTRL + 3584);   // 128 f

    if (tid < 256) b_s[tid] = bias[tid];

    const unsigned aHiB = smb + AHI + (wm * 32 + (lane & 15)) * 144 + (lane >> 4) * 16;
    const unsigned aLoB = aHiB + (ALO - AHI);
    const unsigned bHiB = smb + BHI + (wn * 64 + (lane & 15)) * 144 + (lane >> 4) * 16;
    const unsigned bLoB = bHiB + (BLO - BHI);

    // A load geometry for this thread (row r, 16-float segment seg)
    const int ar = tid >> 2, aseg = tid & 3;
    const float* aptr = x + (row0 + ar) * 256 + aseg * 16;

    float acc[16][4];
    #pragma unroll
    for (int i = 0; i < 16; i++)
        #pragma unroll
        for (int j = 0; j < 4; j++) acc[i][j] = 0.f;

    float ssx = 0.f;

    // prologue: B0 in flight; convert A chunk0 from LDG regs into stage 0.
    issueB(smb, tid, 0, 0);
    CP_COMMIT();
    {
        float4 a0[4];
        #pragma unroll
        for (int i = 0; i < 4; i++) a0[i] = *(const float4*)(aptr + i * 4);
        convertRegs(sm, tid, 0, a0, ssx);
    }

    // ------------------------- mainloop: 4 K-chunks -------------------------
    #pragma unroll 1
    for (int c = 0; c < 4; c++) {
        const int s = c & 1;
        CP_WAIT0();                   // B(c) landed
        __syncthreads();              // B(c) + convA(c) visible to all

        float4 anx[4];
        if (c < 3) {
            issueB(smb, tid, c + 1, s ^ 1);
            CP_COMMIT();
            const float* ap = aptr + (c + 1) * 64;
            #pragma unroll
            for (int i = 0; i < 4; i++) anx[i] = *(const float4*)(ap + i * 4);
        }

        const unsigned aH = aHiB + s * A_ST;
        const unsigned aL = aLoB + s * A_ST;
        const unsigned bH = bHiB + s * B_ST;
        const unsigned bL = bLoB + s * B_ST;
        #pragma unroll
        for (int k16 = 0; k16 < 4; k16++) {
            unsigned ah[2][4], al[2][4];
            #pragma unroll
            for (int mi = 0; mi < 2; mi++) {
                LDSM4(ah[mi], aH + mi * 2304 + k16 * 32);
                LDSM4(al[mi], aL + mi * 2304 + k16 * 32);
            }
            #pragma unroll
            for (int nn = 0; nn < 4; nn++) {
                unsigned bh[4], bl[4];
                LDSM4(bh, bH + nn * 2304 + k16 * 32);
                LDSM4(bl, bL + nn * 2304 + k16 * 32);
                #pragma unroll
                for (int mi = 0; mi < 2; mi++) {
                    #pragma unroll
                    for (int hn = 0; hn < 2; hn++) {
                        float* d = acc[mi * 8 + nn * 2 + hn];
                        MMA(d, ah[mi], bh[hn], bh[hn + 2]);
                        MMA(d, ah[mi], bl[hn], bl[hn + 2]);
                        MMA(d, al[mi], bh[hn], bh[hn + 2]);
                    }
                }
            }
            // mid-loop: convert next-chunk A regs into the other stage
            if (k16 == 1 && c < 3)
                convertRegs(sm, tid, s ^ 1, anx, ssx);
        }
    }

    // log-map scale per row (4 lanes share row ar)
    {
        float t = ssx;
        t += __shfl_xor_sync(0xffffffffu, t, 1);
        t += __shfl_xor_sync(0xffffffffu, t, 2);
        if ((tid & 3) == 0) {
            float xn = fmaxf(sqrtf(t), 1e-6f);
            float sc = fminf(0.1f * xn, 1.0f - 1e-6f);
            xscale_s[ar] = atanhf(sc) / (0.1f * xn);
        }
    }
    __syncthreads();

    // ------------------------- epilogue -------------------------
    const int rsub = lane >> 2;
    float xs[2][2];
    #pragma unroll
    for (int mi = 0; mi < 2; mi++)
        #pragma unroll
        for (int h = 0; h < 2; h++)
            xs[mi][h] = xscale_s[wm * 32 + mi * 16 + h * 8 + rsub];

    float2 bb[8];
    #pragma unroll
    for (int ni = 0; ni < 8; ni++) {
        int col = wn * 64 + ni * 8 + (lane & 3) * 2;
        bb[ni] = make_float2(b_s[col], b_s[col + 1]);
    }

    float ss[2][2] = {{0.f, 0.f}, {0.f, 0.f}};
    #pragma unroll
    for (int mi = 0; mi < 2; mi++) {
        #pragma unroll
        for (int ni = 0; ni < 8; ni++) {
            float* d = acc[mi * 8 + ni];
            float v0 = fmaf(d[0], xs[mi][0], bb[ni].x);
            float v1 = fmaf(d[1], xs[mi][0], bb[ni].y);
            float v2 = fmaf(d[2], xs[mi][1], bb[ni].x);
            float v3 = fmaf(d[3], xs[mi][1], bb[ni].y);
            d[0] = v0; d[1] = v1; d[2] = v2; d[3] = v3;
            ss[mi][0] = fmaf(v0, v0, fmaf(v1, v1, ss[mi][0]));
            ss[mi][1] = fmaf(v2, v2, fmaf(v3, v3, ss[mi][1]));
        }
    }
    #pragma unroll
    for (int mi = 0; mi < 2; mi++)
        #pragma unroll
        for (int h = 0; h < 2; h++) {
            float t = ss[mi][h];
            t += __shfl_xor_sync(0xffffffffu, t, 1);
            t += __shfl_xor_sync(0xffffffffu, t, 2);
            if ((lane & 3) == 0)
                part_s[wn * 128 + wm * 32 + mi * 16 + h * 8 + rsub] = t;
        }
    __syncthreads();
    if (tid < 128) {
        float tot = part_s[tid] + part_s[128 + tid] + part_s[256 + tid] + part_s[384 + tid];
        float vn = fmaxf(sqrtf(tot), 1e-6f);
        float g  = tanhf(0.1f * vn) / (0.1f * vn);
        float rn = fmaxf(g * vn, 1e-6f);
        float cl = fminf(rn, 10.0f - 2e-6f);
        factor_s[tid] = g * (cl / rn);
    }
    __syncthreads();

    #pragma unroll
    for (int mi = 0; mi < 2; mi++) {
        #pragma unroll
        for (int h = 0; h < 2; h++) {
            const int row = wm * 32 + mi * 16 + h * 8 + rsub;
            const float f = factor_s[row];
            float* orow = out + (row0 + row) * 256;
            #pragma unroll
            for (int ni = 0; ni < 8; ni++) {
                float* d = acc[mi * 8 + ni];
                int col = wn * 64 + ni * 8 + (lane & 3) * 2;
                float2 o;
                o.x = d[h * 2]     * f;
                o.y = d[h * 2 + 1] * f;
                *(float2*)(orow + col) = o;
            }
        }
    }
}

extern "C" void kernel_launch(void* const* d_in, const int* in_sizes, int n_in,
                              void* d_out, int out_size)
{
    const float* x = (const float*)d_in[0];
    const float* W = (const float*)d_in[1];
    const float* b = (const float*)d_in[2];
    float* out = (float*)d_out;

    prep_W_kernel<<<256, 256>>>(W);

    cudaFuncSetAttribute(hyper_hmma_kernel,
                         cudaFuncAttributeMaxDynamicSharedMemorySize, SMEM_BYTES);
    const int nrows = in_sizes[0] / 256;
    hyper_hmma_kernel<<<nrows / 128, NT, SMEM_BYTES>>>(x, b, out);
}